// round 13
// baseline (speedup 1.0000x reference)
#include <cuda_runtime.h>
#include <cuda_bf16.h>
#include <stdint.h>

// NeRF fused MLP via mma.sync (HMMA) bf16 hi/lo split-3, m=1 per warp.
// R13: fully software-pipelined X-phase — tile t+1's s0 A-fragments and view
// stash are built mid-way through tile t's color net, so the loop head has no
// memory-dependent serial work. V frags live in per-warp SMEM.

#define XDIM 48

// frag-order smem byte offsets: layer size = KT*NT*32*16
#define S0F 0        // KT2 NT8:  8192
#define S1F 8192     // KT4 NT8: 16384
#define S2F 24576    // KT4 NT2:  4096
#define C0F 28672    // KT2 NT8:  8192
#define C1F 36864    // KT4 NT8: 16384
#define C2F 53248    // KT4 NT8: 16384
#define C3F 69632    // KT4 NT1:  4096
#define XBUF 73728   // 8 warps * 16 rows * 208B = 26624
#define XROWB 208
#define XWARPB 3328
#define VOUT 100352  // 8 warps * 1280B: [0,1024) V stash, [1024,1280) out stash
#define VWARPB 1280
#define SMEM_TOTAL 110592

__device__ __forceinline__ uint32_t smem_u32(const void* p) {
    uint32_t a;
    asm("{ .reg .u64 t; cvta.to.shared.u64 t, %1; cvt.u32.u64 %0, t; }"
        : "=r"(a) : "l"(p));
    return a;
}
__device__ __forceinline__ uint4 lds128(uint32_t a) {
    uint4 v;
    asm volatile("ld.shared.v4.b32 {%0,%1,%2,%3}, [%4];"
                 : "=r"(v.x), "=r"(v.y), "=r"(v.z), "=r"(v.w) : "r"(a));
    return v;
}
__device__ __forceinline__ void sts128(uint32_t a, uint4 v) {
    asm volatile("st.shared.v4.b32 [%0], {%1,%2,%3,%4};"
                 :: "r"(a), "r"(v.x), "r"(v.y), "r"(v.z), "r"(v.w) : "memory");
}
__device__ __forceinline__ float2 lds_f2(uint32_t a) {
    float2 v;
    asm volatile("ld.shared.v2.f32 {%0,%1}, [%2];"
                 : "=f"(v.x), "=f"(v.y) : "r"(a));
    return v;
}
__device__ __forceinline__ void sts_f(uint32_t a, float v) {
    asm volatile("st.shared.f32 [%0], %1;" :: "r"(a), "f"(v) : "memory");
}
__device__ __forceinline__ float4 lds_f4v(uint32_t a) {
    float4 v;
    asm volatile("ld.shared.v4.f32 {%0,%1,%2,%3}, [%4];"
                 : "=f"(v.x), "=f"(v.y), "=f"(v.z), "=f"(v.w) : "r"(a));
    return v;
}
__device__ __forceinline__ void cp_async16(uint32_t dst, const void* src) {
    asm volatile("cp.async.cg.shared.global [%0], [%1], 16;"
                 :: "r"(dst), "l"(src) : "memory");
}
#define CP_COMMIT() asm volatile("cp.async.commit_group;" ::: "memory")
#define CP_WAIT0()  asm volatile("cp.async.wait_group 0;" ::: "memory")

__device__ __forceinline__ void mma_bf16(float* d, const uint32_t* a,
                                         uint32_t b0, uint32_t b1) {
    asm("mma.sync.aligned.m16n8k16.row.col.f32.bf16.bf16.f32 "
        "{%0,%1,%2,%3},{%4,%5,%6,%7},{%8,%9},{%0,%1,%2,%3};"
        : "+f"(d[0]), "+f"(d[1]), "+f"(d[2]), "+f"(d[3])
        : "r"(a[0]), "r"(a[1]), "r"(a[2]), "r"(a[3]), "r"(b0), "r"(b1));
}
// first MMA of a chain: accumulate from a zero scalar (d != c form)
__device__ __forceinline__ void mma_bf16_z(float* d, const uint32_t* a,
                                           uint32_t b0, uint32_t b1, float z) {
    asm("mma.sync.aligned.m16n8k16.row.col.f32.bf16.bf16.f32 "
        "{%0,%1,%2,%3},{%4,%5,%6,%7},{%8,%9},{%10,%10,%10,%10};"
        : "=f"(d[0]), "=f"(d[1]), "=f"(d[2]), "=f"(d[3])
        : "r"(a[0]), "r"(a[1]), "r"(a[2]), "r"(a[3]), "r"(b0), "r"(b1), "f"(z));
}

// exact truncation split: hi = bits(a)&0xFFFF0000 (exact bf16), lo = bf16(a-hi)
#define SPLIT2(a0, a1, H, L) do { \
    float _s0 = (a0), _s1 = (a1); \
    uint32_t _b0 = __float_as_uint(_s0); \
    uint32_t _b1 = __float_as_uint(_s1); \
    (H) = __byte_perm(_b0, _b1, 0x7632); \
    float _r0 = _s0 - __uint_as_float(_b0 & 0xFFFF0000u); \
    float _r1 = _s1 - __uint_as_float(_b1 & 0xFFFF0000u); \
    __nv_bfloat162 _lb = __floats2bfloat162_rn(_r0, _r1); \
    (L) = *reinterpret_cast<uint32_t*>(&_lb); \
} while (0)

#define RELU_SPLIT2(a0, a1, H, L) SPLIT2(fmaxf((a0), 0.0f), fmaxf((a1), 0.0f), H, L)

// stage a plain [K][N] row-major weight matrix into fragment order
__device__ __forceinline__ void stage_plain(const float* __restrict__ W, int N,
                                            int KT, int NT, char* dst, int tid) {
    const int total = KT * NT * 32;
    for (int idx = tid; idx < total; idx += 256) {
        int lane = idx & 31;
        int grp = idx >> 5;
        int nt = grp % NT, kt = grp / NT;
        int q = lane & 3, nr = lane >> 2;
        int nn = nt * 8 + nr;
        int k0 = kt * 16 + 2 * q;
        float w00 = W[k0 * N + nn],       w01 = W[(k0 + 1) * N + nn];
        float w10 = W[(k0 + 8) * N + nn], w11 = W[(k0 + 9) * N + nn];
        uint4 f;
        SPLIT2(w00, w01, f.x, f.z);
        SPLIT2(w10, w11, f.y, f.w);
        reinterpret_cast<uint4*>(dst)[idx] = f;
    }
}

// GEMM: KT k16-tiles x NT n8-tiles, split-3; k==0 uses zero-source MMA
#define GEMM_LAYER(Dv, Ahv, Alv, KT, NT, OFF) do { \
    _Pragma("unroll") \
    for (int k = 0; k < (KT); k++) { \
        _Pragma("unroll") \
        for (int nt = 0; nt < (NT); nt++) { \
            uint4 _b = lds128(sb + (OFF) + \
                (uint32_t)(((k * (NT) + nt) * 32 + lane) * 16)); \
            if (k == 0) mma_bf16_z(Dv[nt], Ahv[0], _b.x, _b.y, zr); \
            else        mma_bf16(Dv[nt], Ahv[k], _b.x, _b.y); \
            mma_bf16(Dv[nt], Ahv[k], _b.z, _b.w); \
            mma_bf16(Dv[nt], Alv[k], _b.x, _b.y); \
        } \
    } \
} while (0)

// relu + split D[8][4] -> Ah/Al[4][4]
#define EPI_RELU(Dv, Ahv, Alv) do { \
    _Pragma("unroll") \
    for (int j = 0; j < 4; j++) { \
        RELU_SPLIT2(Dv[2*j][0],   Dv[2*j][1],   Ahv[j][0], Alv[j][0]); \
        RELU_SPLIT2(Dv[2*j][2],   Dv[2*j][3],   Ahv[j][1], Alv[j][1]); \
        RELU_SPLIT2(Dv[2*j+1][0], Dv[2*j+1][1], Ahv[j][2], Alv[j][2]); \
        RELU_SPLIT2(Dv[2*j+1][2], Dv[2*j+1][3], Ahv[j][3], Alv[j][3]); \
    } \
} while (0)

__global__ void __launch_bounds__(256, 2)
nerf_hmma10_kernel(const float* __restrict__ x,
                   const float* __restrict__ s0, const float* __restrict__ s1,
                   const float* __restrict__ s2, const float* __restrict__ c0,
                   const float* __restrict__ c1, const float* __restrict__ c2,
                   const float* __restrict__ c3,
                   float* __restrict__ out, int n) {
    extern __shared__ char sm[];
    const uint32_t sb = smem_u32(sm);

    const int tid = threadIdx.x;
    const int wid = tid >> 5;      // 0..7
    const int lane = tid & 31;
    const int q = lane & 3;
    const int nrow = lane >> 2;
    const float zr = 0.0f;

    // ---------- stage split weights in fragment order ----------
    stage_plain(s0, 64, 2, 8, sm + S0F, tid);
    stage_plain(s1, 64, 4, 8, sm + S1F, tid);
    stage_plain(s2, 16, 4, 2, sm + S2F, tid);
    stage_plain(c1, 64, 4, 8, sm + C1F, tid);
    stage_plain(c2, 64, 4, 8, sm + C2F, tid);
    // c0: cat layout [views(16) | zero-row@16 | geo(15)] => K=32
    {
        const int total = 2 * 8 * 32;
        for (int idx = tid; idx < total; idx += 256) {
            int lane2 = idx & 31;
            int grp = idx >> 5;
            int nt = grp % 8, kt = grp / 8;
            int q2 = lane2 & 3, nr = lane2 >> 2;
            int nn = nt * 8 + nr;
            int k0 = kt * 16 + 2 * q2;
            auto w = [&](int k) -> float {
                return (k < 16) ? c0[k * 64 + nn]
                                : ((k == 16) ? 0.0f : c0[(k - 1) * 64 + nn]);
            };
            uint4 f;
            SPLIT2(w(k0),     w(k0 + 1), f.x, f.z);
            SPLIT2(w(k0 + 8), w(k0 + 9), f.y, f.w);
            reinterpret_cast<uint4*>(sm + C0F)[idx] = f;
        }
    }
    // c3: K=64, N pad 3->8
    {
        const int total = 4 * 1 * 32;
        for (int idx = tid; idx < total; idx += 256) {
            int lane2 = idx & 31;
            int kt = idx >> 5;
            int q2 = lane2 & 3, nr = lane2 >> 2;
            int k0 = kt * 16 + 2 * q2;
            float w00 = (nr < 3) ? c3[k0 * 3 + nr] : 0.0f;
            float w01 = (nr < 3) ? c3[(k0 + 1) * 3 + nr] : 0.0f;
            float w10 = (nr < 3) ? c3[(k0 + 8) * 3 + nr] : 0.0f;
            float w11 = (nr < 3) ? c3[(k0 + 9) * 3 + nr] : 0.0f;
            uint4 f;
            SPLIT2(w00, w01, f.x, f.z);
            SPLIT2(w10, w11, f.y, f.w);
            reinterpret_cast<uint4*>(sm + C3F)[idx] = f;
        }
    }
    __syncthreads();

    // ---------- persistent warp-phase stagger ----------
    {
        int slot = (wid + (int)blockIdx.x) % 7;
        float dacc = 1.0f;
        for (int i = 0; i < slot * 30; i++)
            asm volatile("fma.rn.f32 %0, %0, 0f3F7FBE77, 0f3A83126F;"
                         : "+f"(dacc));
        if (__float_as_uint(dacc) == 0xDEADBEEFu)
            sts_f(sb + VOUT, dacc);   // never executes
    }

    const int ntiles = (n + 127) >> 7;
    const uint32_t xb = sb + XBUF + (uint32_t)wid * XWARPB;
    const uint32_t vaddr = sb + VOUT + (uint32_t)wid * VWARPB +
                           (uint32_t)lane * 32;
    const uint32_t outs = sb + VOUT + (uint32_t)wid * VWARPB + 1024;

    // prefetch X for this warp's 16 rows of a tile into its private buffer
    auto prefetch = [&](int tile) {
        int base_r = tile * 128 + wid * 16;
#pragma unroll
        for (int j = 0; j < 6; j++) {
            int c = lane + 32 * j;          // 0..191
            int row = c / 12, col = c % 12; // 12 x 16B chunks per 48-float row
            int r = base_r + row;
            if (r >= n) r = n - 1;
            const char* src = (const char*)(x + (size_t)r * XDIM) + col * 16;
            cp_async16(xb + (uint32_t)(row * XROWB + col * 16), src);
        }
    };

    uint32_t Ah2[2][4], Al2[2][4];   // prebuilt s0 fragments for next tile

    // build s0 A-fragments + V stash from staged XBUF contents
    auto build_frags = [&]() {
        uint32_t a0 = xb + (uint32_t)nrow * XROWB;
        uint32_t a1 = a0 + 8u * XROWB;
#pragma unroll
        for (int t = 0; t < 2; t++) {
            float2 a00 = lds_f2(a0 + 64 * t + 8 * q);
            float2 a10 = lds_f2(a1 + 64 * t + 8 * q);
            float2 a01 = lds_f2(a0 + 64 * t + 8 * q + 32);
            float2 a11 = lds_f2(a1 + 64 * t + 8 * q + 32);
            SPLIT2(a00.x, a00.y, Ah2[t][0], Al2[t][0]);
            SPLIT2(a10.x, a10.y, Ah2[t][1], Al2[t][1]);
            SPLIT2(a01.x, a01.y, Ah2[t][2], Al2[t][2]);
            SPLIT2(a11.x, a11.y, Ah2[t][3], Al2[t][3]);
        }
        float2 v00 = lds_f2(a0 + 128 + 8 * q);
        float2 v10 = lds_f2(a1 + 128 + 8 * q);
        float2 v01 = lds_f2(a0 + 160 + 8 * q);
        float2 v11 = lds_f2(a1 + 160 + 8 * q);
        uint4 vh4, vl4;
        SPLIT2(v00.x, v00.y, vh4.x, vl4.x);
        SPLIT2(v10.x, v10.y, vh4.y, vl4.y);
        SPLIT2(v01.x, v01.y, vh4.z, vl4.z);
        SPLIT2(v11.x, v11.y, vh4.w, vl4.w);
        sts128(vaddr, vh4);
        sts128(vaddr + 16, vl4);
    };

    // ---------- pipeline prologue: stage + build tile0, prefetch tile1 ----------
    int tile = blockIdx.x;
    if (tile < ntiles) {
        prefetch(tile);
        CP_COMMIT();
        CP_WAIT0();
        __syncwarp();
        build_frags();
        __syncwarp();
        int nxt = tile + gridDim.x;
        if (nxt < ntiles) prefetch(nxt);
        CP_COMMIT();
    }

    for (; tile < ntiles; tile += gridDim.x) {
        const int base = tile * 128 + wid * 16;

        uint32_t Ah[4][4], Al[4][4];
        float D[8][4];
        float sigL, sigH;

        // ---------- sigma net (s0 consumes prebuilt Ah2/Al2 directly) ----------
        GEMM_LAYER(D, Ah2, Al2, 2, 8, S0F);
        EPI_RELU(D, Ah, Al);
        GEMM_LAYER(D, Ah, Al, 4, 8, S1F);
        EPI_RELU(D, Ah, Al);
        GEMM_LAYER(D, Ah, Al, 4, 2, S2F);

        // sigma + cat = [views | s2out raw (col0 hits zero weight row)]
        sigL = D[0][0];
        sigH = D[0][2];
        SPLIT2(D[0][0], D[0][1], Ah[1][0], Al[1][0]);
        SPLIT2(D[0][2], D[0][3], Ah[1][1], Al[1][1]);
        SPLIT2(D[1][0], D[1][1], Ah[1][2], Al[1][2]);
        SPLIT2(D[1][2], D[1][3], Ah[1][3], Al[1][3]);
        {
            uint4 vh4 = lds128(vaddr);
            uint4 vl4 = lds128(vaddr + 16);
            Ah[0][0] = vh4.x; Ah[0][1] = vh4.y; Ah[0][2] = vh4.z; Ah[0][3] = vh4.w;
            Al[0][0] = vl4.x; Al[0][1] = vl4.y; Al[0][2] = vl4.z; Al[0][3] = vl4.w;
        }

        // ---------- color net ----------
        GEMM_LAYER(D, Ah, Al, 2, 8, C0F);
        EPI_RELU(D, Ah, Al);

        // ---- mid-pipeline: build NEXT tile's fragments under c1..c3 MMAs ----
        {
            int nt2 = tile + gridDim.x;
            if (nt2 < ntiles) {
                CP_WAIT0();
                __syncwarp();
                build_frags();        // V(t) already consumed at CAT above
                __syncwarp();
                int nt3 = nt2 + gridDim.x;
                if (nt3 < ntiles) prefetch(nt3);
                CP_COMMIT();
            }
        }

        GEMM_LAYER(D, Ah, Al, 4, 8, C1F);
        EPI_RELU(D, Ah, Al);
        GEMM_LAYER(D, Ah, Al, 4, 8, C2F);
        EPI_RELU(D, Ah, Al);
        GEMM_LAYER(D, Ah, Al, 4, 1, C3F);

        // ---------- output via warp-local SMEM scratch, coalesced f4 ----------
        {
            uint32_t s0a = outs + (uint32_t)nrow * 16;
            uint32_t s1a = s0a + 8 * 16;
            if (q == 0) {
                sts_f(s0a + 0,  D[0][0]);
                sts_f(s0a + 4,  D[0][1]);
                sts_f(s0a + 12, sigL);
                sts_f(s1a + 0,  D[0][2]);
                sts_f(s1a + 4,  D[0][3]);
                sts_f(s1a + 12, sigH);
            } else if (q == 1) {
                sts_f(s0a + 8, D[0][0]);
                sts_f(s1a + 8, D[0][2]);
            }
        }
        __syncwarp();
        if (lane < 16) {
            int orow = base + lane;
            if (orow < n) {
                float4 v = lds_f4v(outs + (uint32_t)lane * 16);
                reinterpret_cast<float4*>(out)[orow] = v;
            }
        }
        __syncwarp();
    }
}

extern "C" void kernel_launch(void* const* d_in, const int* in_sizes, int n_in,
                              void* d_out, int out_size) {
    const float* x  = (const float*)d_in[0];
    const float* s0 = (const float*)d_in[1];
    const float* s1 = (const float*)d_in[2];
    const float* s2 = (const float*)d_in[3];
    const float* c0 = (const float*)d_in[4];
    const float* c1 = (const float*)d_in[5];
    const float* c2 = (const float*)d_in[6];
    const float* c3 = (const float*)d_in[7];
    float* out = (float*)d_out;

    const int n = in_sizes[0] / XDIM;

    cudaFuncSetAttribute(nerf_hmma10_kernel,
                         cudaFuncAttributeMaxDynamicSharedMemorySize, SMEM_TOTAL);

    int occ = 0;
    cudaOccupancyMaxActiveBlocksPerMultiprocessor(&occ, nerf_hmma10_kernel, 256,
                                                  SMEM_TOTAL);
    if (occ < 1) occ = 1;
    int blocks = 152 * occ;

    nerf_hmma10_kernel<<<blocks, 256, SMEM_TOTAL>>>(x, s0, s1, s2, c0, c1, c2,
                                                    c3, out, n);
}

// round 14
// speedup vs baseline: 1.0563x; 1.0563x over previous
#include <cuda_runtime.h>
#include <cuda_bf16.h>
#include <stdint.h>

// NeRF fused MLP via mma.sync (HMMA) bf16 hi/lo split-3, m=1 per warp.
// R14: c3 (64->3) moved off the tensor pipe onto FMA (exact fp32, -12 MMAs
// per warp-tile) with q-group shfl reduction and direct STG.128 output.
// Base: R10 (best, 475us): cp.async X prefetch, zero-source first MMA,
// warp-phase stagger.

#define XDIM 48

// frag-order smem byte offsets: layer size = KT*NT*32*16
#define S0F 0        // KT2 NT8:  8192
#define S1F 8192     // KT4 NT8: 16384
#define S2F 24576    // KT4 NT2:  4096
#define C0F 28672    // KT2 NT8:  8192
#define C1F 36864    // KT4 NT8: 16384
#define C2F 53248    // KT4 NT8: 16384
#define C3R 69632    // c3 raw fp32 [k][4] pad: 64*16 = 1024
#define XBUF 73728   // 8 warps * 16 rows * 208B = 26624
#define XROWB 208
#define XWARPB 3328
#define SMEM_TOTAL 102400

__device__ __forceinline__ uint32_t smem_u32(const void* p) {
    uint32_t a;
    asm("{ .reg .u64 t; cvta.to.shared.u64 t, %1; cvt.u32.u64 %0, t; }"
        : "=r"(a) : "l"(p));
    return a;
}
__device__ __forceinline__ uint4 lds128(uint32_t a) {
    uint4 v;
    asm volatile("ld.shared.v4.b32 {%0,%1,%2,%3}, [%4];"
                 : "=r"(v.x), "=r"(v.y), "=r"(v.z), "=r"(v.w) : "r"(a));
    return v;
}
__device__ __forceinline__ float2 lds_f2(uint32_t a) {
    float2 v;
    asm volatile("ld.shared.v2.f32 {%0,%1}, [%2];"
                 : "=f"(v.x), "=f"(v.y) : "r"(a));
    return v;
}
__device__ __forceinline__ void sts_f(uint32_t a, float v) {
    asm volatile("st.shared.f32 [%0], %1;" :: "r"(a), "f"(v) : "memory");
}
__device__ __forceinline__ float4 lds_f4v(uint32_t a) {
    float4 v;
    asm volatile("ld.shared.v4.f32 {%0,%1,%2,%3}, [%4];"
                 : "=f"(v.x), "=f"(v.y), "=f"(v.z), "=f"(v.w) : "r"(a));
    return v;
}
__device__ __forceinline__ void cp_async16(uint32_t dst, const void* src) {
    asm volatile("cp.async.cg.shared.global [%0], [%1], 16;"
                 :: "r"(dst), "l"(src) : "memory");
}
#define CP_COMMIT() asm volatile("cp.async.commit_group;" ::: "memory")
#define CP_WAIT0()  asm volatile("cp.async.wait_group 0;" ::: "memory")

__device__ __forceinline__ void mma_bf16(float* d, const uint32_t* a,
                                         uint32_t b0, uint32_t b1) {
    asm("mma.sync.aligned.m16n8k16.row.col.f32.bf16.bf16.f32 "
        "{%0,%1,%2,%3},{%4,%5,%6,%7},{%8,%9},{%0,%1,%2,%3};"
        : "+f"(d[0]), "+f"(d[1]), "+f"(d[2]), "+f"(d[3])
        : "r"(a[0]), "r"(a[1]), "r"(a[2]), "r"(a[3]), "r"(b0), "r"(b1));
}
// first MMA of a chain: accumulate from a zero scalar (d != c form)
__device__ __forceinline__ void mma_bf16_z(float* d, const uint32_t* a,
                                           uint32_t b0, uint32_t b1, float z) {
    asm("mma.sync.aligned.m16n8k16.row.col.f32.bf16.bf16.f32 "
        "{%0,%1,%2,%3},{%4,%5,%6,%7},{%8,%9},{%10,%10,%10,%10};"
        : "=f"(d[0]), "=f"(d[1]), "=f"(d[2]), "=f"(d[3])
        : "r"(a[0]), "r"(a[1]), "r"(a[2]), "r"(a[3]), "r"(b0), "r"(b1), "f"(z));
}

// exact truncation split: hi = bits(a)&0xFFFF0000 (exact bf16), lo = bf16(a-hi)
#define SPLIT2(a0, a1, H, L) do { \
    float _s0 = (a0), _s1 = (a1); \
    uint32_t _b0 = __float_as_uint(_s0); \
    uint32_t _b1 = __float_as_uint(_s1); \
    (H) = __byte_perm(_b0, _b1, 0x7632); \
    float _r0 = _s0 - __uint_as_float(_b0 & 0xFFFF0000u); \
    float _r1 = _s1 - __uint_as_float(_b1 & 0xFFFF0000u); \
    __nv_bfloat162 _lb = __floats2bfloat162_rn(_r0, _r1); \
    (L) = *reinterpret_cast<uint32_t*>(&_lb); \
} while (0)

#define RELU_SPLIT2(a0, a1, H, L) SPLIT2(fmaxf((a0), 0.0f), fmaxf((a1), 0.0f), H, L)

// stage a plain [K][N] row-major weight matrix into fragment order
__device__ __forceinline__ void stage_plain(const float* __restrict__ W, int N,
                                            int KT, int NT, char* dst, int tid) {
    const int total = KT * NT * 32;
    for (int idx = tid; idx < total; idx += 256) {
        int lane = idx & 31;
        int grp = idx >> 5;
        int nt = grp % NT, kt = grp / NT;
        int q = lane & 3, nr = lane >> 2;
        int nn = nt * 8 + nr;
        int k0 = kt * 16 + 2 * q;
        float w00 = W[k0 * N + nn],       w01 = W[(k0 + 1) * N + nn];
        float w10 = W[(k0 + 8) * N + nn], w11 = W[(k0 + 9) * N + nn];
        uint4 f;
        SPLIT2(w00, w01, f.x, f.z);
        SPLIT2(w10, w11, f.y, f.w);
        reinterpret_cast<uint4*>(dst)[idx] = f;
    }
}

// GEMM: KT k16-tiles x NT n8-tiles, split-3; k==0 uses zero-source MMA
#define GEMM_LAYER(Dv, Ahv, Alv, KT, NT, OFF) do { \
    _Pragma("unroll") \
    for (int k = 0; k < (KT); k++) { \
        _Pragma("unroll") \
        for (int nt = 0; nt < (NT); nt++) { \
            uint4 _b = lds128(sb + (OFF) + \
                (uint32_t)(((k * (NT) + nt) * 32 + lane) * 16)); \
            if (k == 0) mma_bf16_z(Dv[nt], Ahv[0], _b.x, _b.y, zr); \
            else        mma_bf16(Dv[nt], Ahv[k], _b.x, _b.y); \
            mma_bf16(Dv[nt], Ahv[k], _b.z, _b.w); \
            mma_bf16(Dv[nt], Alv[k], _b.x, _b.y); \
        } \
    } \
} while (0)

// relu + split D[8][4] -> Ah/Al[4][4]
#define EPI_RELU(Dv, Ahv, Alv) do { \
    _Pragma("unroll") \
    for (int j = 0; j < 4; j++) { \
        RELU_SPLIT2(Dv[2*j][0],   Dv[2*j][1],   Ahv[j][0], Alv[j][0]); \
        RELU_SPLIT2(Dv[2*j][2],   Dv[2*j][3],   Ahv[j][1], Alv[j][1]); \
        RELU_SPLIT2(Dv[2*j+1][0], Dv[2*j+1][1], Ahv[j][2], Alv[j][2]); \
        RELU_SPLIT2(Dv[2*j+1][2], Dv[2*j+1][3], Ahv[j][3], Alv[j][3]); \
    } \
} while (0)

__global__ void __launch_bounds__(256, 2)
nerf_hmma11_kernel(const float* __restrict__ x,
                   const float* __restrict__ s0, const float* __restrict__ s1,
                   const float* __restrict__ s2, const float* __restrict__ c0,
                   const float* __restrict__ c1, const float* __restrict__ c2,
                   const float* __restrict__ c3,
                   float* __restrict__ out, int n) {
    extern __shared__ char sm[];
    const uint32_t sb = smem_u32(sm);

    const int tid = threadIdx.x;
    const int wid = tid >> 5;      // 0..7
    const int lane = tid & 31;
    const int q = lane & 3;
    const int nrow = lane >> 2;
    const float zr = 0.0f;

    // ---------- stage split weights in fragment order ----------
    stage_plain(s0, 64, 2, 8, sm + S0F, tid);
    stage_plain(s1, 64, 4, 8, sm + S1F, tid);
    stage_plain(s2, 16, 4, 2, sm + S2F, tid);
    stage_plain(c1, 64, 4, 8, sm + C1F, tid);
    stage_plain(c2, 64, 4, 8, sm + C2F, tid);
    // c0: cat layout [views(16) | zero-row@16 | geo(15)] => K=32
    {
        const int total = 2 * 8 * 32;
        for (int idx = tid; idx < total; idx += 256) {
            int lane2 = idx & 31;
            int grp = idx >> 5;
            int nt = grp % 8, kt = grp / 8;
            int q2 = lane2 & 3, nr = lane2 >> 2;
            int nn = nt * 8 + nr;
            int k0 = kt * 16 + 2 * q2;
            auto w = [&](int k) -> float {
                return (k < 16) ? c0[k * 64 + nn]
                                : ((k == 16) ? 0.0f : c0[(k - 1) * 64 + nn]);
            };
            uint4 f;
            SPLIT2(w(k0),     w(k0 + 1), f.x, f.z);
            SPLIT2(w(k0 + 8), w(k0 + 9), f.y, f.w);
            reinterpret_cast<uint4*>(sm + C0F)[idx] = f;
        }
    }
    // c3 raw fp32, padded [k][4]: {w0, w1, w2, 0} per k row
    for (int k = tid; k < 64; k += 256) {
        float4 w = make_float4(c3[k * 3 + 0], c3[k * 3 + 1], c3[k * 3 + 2], 0.0f);
        reinterpret_cast<float4*>(sm + C3R)[k] = w;
    }
    __syncthreads();

    // ---------- persistent warp-phase stagger ----------
    {
        int slot = (wid + (int)blockIdx.x) % 7;
        float dacc = 1.0f;
        for (int i = 0; i < slot * 30; i++)
            asm volatile("fma.rn.f32 %0, %0, 0f3F7FBE77, 0f3A83126F;"
                         : "+f"(dacc));
        if (__float_as_uint(dacc) == 0xDEADBEEFu)
            sts_f(sb + C3R, dacc);   // never executes
    }

    const int ntiles = (n + 127) >> 7;
    const uint32_t xb = sb + XBUF + (uint32_t)wid * XWARPB;

    // prefetch X for this warp's 16 rows of a tile into its private buffer
    auto prefetch = [&](int tile) {
        int base_r = tile * 128 + wid * 16;
#pragma unroll
        for (int j = 0; j < 6; j++) {
            int c = lane + 32 * j;          // 0..191
            int row = c / 12, col = c % 12; // 12 x 16B chunks per 48-float row
            int r = base_r + row;
            if (r >= n) r = n - 1;
            const char* src = (const char*)(x + (size_t)r * XDIM) + col * 16;
            cp_async16(xb + (uint32_t)(row * XROWB + col * 16), src);
        }
    };

    int tile = blockIdx.x;
    if (tile < ntiles) prefetch(tile);
    CP_COMMIT();

    for (; tile < ntiles; tile += gridDim.x) {
        const int base = tile * 128 + wid * 16;

        uint32_t Ah[4][4], Al[4][4];
        uint32_t Vh[4], Vl[4];
        float D[8][4];
        float sigL, sigH;

        // ---------- consume staged X, build A frags (s0) + view frags ----------
        CP_WAIT0();
        __syncwarp();
        {
            uint32_t a0 = xb + (uint32_t)nrow * XROWB;
            uint32_t a1 = a0 + 8u * XROWB;
#pragma unroll
            for (int t = 0; t < 2; t++) {
                float2 a00 = lds_f2(a0 + 64 * t + 8 * q);
                float2 a10 = lds_f2(a1 + 64 * t + 8 * q);
                float2 a01 = lds_f2(a0 + 64 * t + 8 * q + 32);
                float2 a11 = lds_f2(a1 + 64 * t + 8 * q + 32);
                SPLIT2(a00.x, a00.y, Ah[t][0], Al[t][0]);
                SPLIT2(a10.x, a10.y, Ah[t][1], Al[t][1]);
                SPLIT2(a01.x, a01.y, Ah[t][2], Al[t][2]);
                SPLIT2(a11.x, a11.y, Ah[t][3], Al[t][3]);
            }
            float2 v00 = lds_f2(a0 + 128 + 8 * q);
            float2 v10 = lds_f2(a1 + 128 + 8 * q);
            float2 v01 = lds_f2(a0 + 160 + 8 * q);
            float2 v11 = lds_f2(a1 + 160 + 8 * q);
            SPLIT2(v00.x, v00.y, Vh[0], Vl[0]);
            SPLIT2(v10.x, v10.y, Vh[1], Vl[1]);
            SPLIT2(v01.x, v01.y, Vh[2], Vl[2]);
            SPLIT2(v11.x, v11.y, Vh[3], Vl[3]);
        }
        __syncwarp();

        // kick off next tile's X prefetch; overlaps the whole GEMM chain
        {
            int nxt = tile + gridDim.x;
            if (nxt < ntiles) prefetch(nxt);
            CP_COMMIT();
        }

        // ---------- sigma net ----------
        GEMM_LAYER(D, Ah, Al, 2, 8, S0F);
        EPI_RELU(D, Ah, Al);
        GEMM_LAYER(D, Ah, Al, 4, 8, S1F);
        EPI_RELU(D, Ah, Al);
        GEMM_LAYER(D, Ah, Al, 4, 2, S2F);

        // sigma + cat = [views | s2out raw (col0 hits zero weight row)]
        sigL = D[0][0];
        sigH = D[0][2];
        SPLIT2(D[0][0], D[0][1], Ah[1][0], Al[1][0]);
        SPLIT2(D[0][2], D[0][3], Ah[1][1], Al[1][1]);
        SPLIT2(D[1][0], D[1][1], Ah[1][2], Al[1][2]);
        SPLIT2(D[1][2], D[1][3], Ah[1][3], Al[1][3]);
#pragma unroll
        for (int i = 0; i < 4; i++) { Ah[0][i] = Vh[i]; Al[0][i] = Vl[i]; }

        // ---------- color net ----------
        GEMM_LAYER(D, Ah, Al, 2, 8, C0F);
        EPI_RELU(D, Ah, Al);
        GEMM_LAYER(D, Ah, Al, 4, 8, C1F);
        EPI_RELU(D, Ah, Al);
        GEMM_LAYER(D, Ah, Al, 4, 8, C2F);

        // ---------- c3 (64->3) on the FMA pipe, exact fp32 ----------
        // thread owns cols {8nt+2q, 8nt+2q+1} of relu(h) for rows nrow, nrow+8
        float o0 = 0.f, o1 = 0.f, o2 = 0.f, o3 = 0.f, o4 = 0.f, o5 = 0.f;
#pragma unroll
        for (int nt = 0; nt < 8; nt++) {
            uint32_t wa = sb + C3R + (uint32_t)((nt * 8 + 2 * q) * 16);
            float4 w0 = lds_f4v(wa);
            float4 w1 = lds_f4v(wa + 16);
            float h00 = fmaxf(D[nt][0], 0.f), h01 = fmaxf(D[nt][1], 0.f);
            float h10 = fmaxf(D[nt][2], 0.f), h11 = fmaxf(D[nt][3], 0.f);
            o0 = fmaf(h00, w0.x, fmaf(h01, w1.x, o0));
            o1 = fmaf(h00, w0.y, fmaf(h01, w1.y, o1));
            o2 = fmaf(h00, w0.z, fmaf(h01, w1.z, o2));
            o3 = fmaf(h10, w0.x, fmaf(h11, w1.x, o3));
            o4 = fmaf(h10, w0.y, fmaf(h11, w1.y, o4));
            o5 = fmaf(h10, w0.z, fmaf(h11, w1.z, o5));
        }
        // reduce across the 4-lane q-group (lanes q=0..3 hold disjoint cols)
#pragma unroll
        for (int d = 1; d < 4; d <<= 1) {
            o0 += __shfl_xor_sync(0xFFFFFFFFu, o0, d);
            o1 += __shfl_xor_sync(0xFFFFFFFFu, o1, d);
            o2 += __shfl_xor_sync(0xFFFFFFFFu, o2, d);
            o3 += __shfl_xor_sync(0xFFFFFFFFu, o3, d);
            o4 += __shfl_xor_sync(0xFFFFFFFFu, o4, d);
            o5 += __shfl_xor_sync(0xFFFFFFFFu, o5, d);
        }

        // ---------- direct output: q==0 lanes hold complete rows ----------
        if (q == 0) {
            int r0 = base + nrow;
            int r1 = r0 + 8;
            if (r0 < n)
                reinterpret_cast<float4*>(out)[r0] = make_float4(o0, o1, o2, sigL);
            if (r1 < n)
                reinterpret_cast<float4*>(out)[r1] = make_float4(o3, o4, o5, sigH);
        }
    }
}

extern "C" void kernel_launch(void* const* d_in, const int* in_sizes, int n_in,
                              void* d_out, int out_size) {
    const float* x  = (const float*)d_in[0];
    const float* s0 = (const float*)d_in[1];
    const float* s1 = (const float*)d_in[2];
    const float* s2 = (const float*)d_in[3];
    const float* c0 = (const float*)d_in[4];
    const float* c1 = (const float*)d_in[5];
    const float* c2 = (const float*)d_in[6];
    const float* c3 = (const float*)d_in[7];
    float* out = (float*)d_out;

    const int n = in_sizes[0] / XDIM;

    cudaFuncSetAttribute(nerf_hmma11_kernel,
                         cudaFuncAttributeMaxDynamicSharedMemorySize, SMEM_TOTAL);

    int occ = 0;
    cudaOccupancyMaxActiveBlocksPerMultiprocessor(&occ, nerf_hmma11_kernel, 256,
                                                  SMEM_TOTAL);
    if (occ < 1) occ = 1;
    int blocks = 152 * occ;

    nerf_hmma11_kernel<<<blocks, 256, SMEM_TOTAL>>>(x, s0, s1, s2, c0, c1, c2,
                                                    c3, out, n);
}

// round 15
// speedup vs baseline: 1.0578x; 1.0015x over previous
#include <cuda_runtime.h>
#include <cuda_bf16.h>
#include <stdint.h>

// NeRF fused MLP via mma.sync (HMMA) bf16 hi/lo split-3, m=1 per warp.
// R15: R14 base (c3 on FMA, exact) with the dead stagger removed and the c3
// FMA reduction interleaved per-nt into c2's GEMM (shortens per-tile tensor
// idle tail). Arithmetic identical to R14.

#define XDIM 48

// frag-order smem byte offsets: layer size = KT*NT*32*16
#define S0F 0        // KT2 NT8:  8192
#define S1F 8192     // KT4 NT8: 16384
#define S2F 24576    // KT4 NT2:  4096
#define C0F 28672    // KT2 NT8:  8192
#define C1F 36864    // KT4 NT8: 16384
#define C2F 53248    // KT4 NT8: 16384
#define C3R 69632    // c3 raw fp32 [k][4] pad: 64*16 = 1024
#define XBUF 73728   // 8 warps * 16 rows * 208B = 26624
#define XROWB 208
#define XWARPB 3328
#define SMEM_TOTAL 102400

__device__ __forceinline__ uint32_t smem_u32(const void* p) {
    uint32_t a;
    asm("{ .reg .u64 t; cvta.to.shared.u64 t, %1; cvt.u32.u64 %0, t; }"
        : "=r"(a) : "l"(p));
    return a;
}
__device__ __forceinline__ uint4 lds128(uint32_t a) {
    uint4 v;
    asm volatile("ld.shared.v4.b32 {%0,%1,%2,%3}, [%4];"
                 : "=r"(v.x), "=r"(v.y), "=r"(v.z), "=r"(v.w) : "r"(a));
    return v;
}
__device__ __forceinline__ float2 lds_f2(uint32_t a) {
    float2 v;
    asm volatile("ld.shared.v2.f32 {%0,%1}, [%2];"
                 : "=f"(v.x), "=f"(v.y) : "r"(a));
    return v;
}
__device__ __forceinline__ float4 lds_f4v(uint32_t a) {
    float4 v;
    asm volatile("ld.shared.v4.f32 {%0,%1,%2,%3}, [%4];"
                 : "=f"(v.x), "=f"(v.y), "=f"(v.z), "=f"(v.w) : "r"(a));
    return v;
}
__device__ __forceinline__ void cp_async16(uint32_t dst, const void* src) {
    asm volatile("cp.async.cg.shared.global [%0], [%1], 16;"
                 :: "r"(dst), "l"(src) : "memory");
}
#define CP_COMMIT() asm volatile("cp.async.commit_group;" ::: "memory")
#define CP_WAIT0()  asm volatile("cp.async.wait_group 0;" ::: "memory")

__device__ __forceinline__ void mma_bf16(float* d, const uint32_t* a,
                                         uint32_t b0, uint32_t b1) {
    asm("mma.sync.aligned.m16n8k16.row.col.f32.bf16.bf16.f32 "
        "{%0,%1,%2,%3},{%4,%5,%6,%7},{%8,%9},{%0,%1,%2,%3};"
        : "+f"(d[0]), "+f"(d[1]), "+f"(d[2]), "+f"(d[3])
        : "r"(a[0]), "r"(a[1]), "r"(a[2]), "r"(a[3]), "r"(b0), "r"(b1));
}
// first MMA of a chain: accumulate from a zero scalar (d != c form)
__device__ __forceinline__ void mma_bf16_z(float* d, const uint32_t* a,
                                           uint32_t b0, uint32_t b1, float z) {
    asm("mma.sync.aligned.m16n8k16.row.col.f32.bf16.bf16.f32 "
        "{%0,%1,%2,%3},{%4,%5,%6,%7},{%8,%9},{%10,%10,%10,%10};"
        : "=f"(d[0]), "=f"(d[1]), "=f"(d[2]), "=f"(d[3])
        : "r"(a[0]), "r"(a[1]), "r"(a[2]), "r"(a[3]), "r"(b0), "r"(b1), "f"(z));
}

// exact truncation split: hi = bits(a)&0xFFFF0000 (exact bf16), lo = bf16(a-hi)
#define SPLIT2(a0, a1, H, L) do { \
    float _s0 = (a0), _s1 = (a1); \
    uint32_t _b0 = __float_as_uint(_s0); \
    uint32_t _b1 = __float_as_uint(_s1); \
    (H) = __byte_perm(_b0, _b1, 0x7632); \
    float _r0 = _s0 - __uint_as_float(_b0 & 0xFFFF0000u); \
    float _r1 = _s1 - __uint_as_float(_b1 & 0xFFFF0000u); \
    __nv_bfloat162 _lb = __floats2bfloat162_rn(_r0, _r1); \
    (L) = *reinterpret_cast<uint32_t*>(&_lb); \
} while (0)

#define RELU_SPLIT2(a0, a1, H, L) SPLIT2(fmaxf((a0), 0.0f), fmaxf((a1), 0.0f), H, L)

// stage a plain [K][N] row-major weight matrix into fragment order
__device__ __forceinline__ void stage_plain(const float* __restrict__ W, int N,
                                            int KT, int NT, char* dst, int tid) {
    const int total = KT * NT * 32;
    for (int idx = tid; idx < total; idx += 256) {
        int lane = idx & 31;
        int grp = idx >> 5;
        int nt = grp % NT, kt = grp / NT;
        int q = lane & 3, nr = lane >> 2;
        int nn = nt * 8 + nr;
        int k0 = kt * 16 + 2 * q;
        float w00 = W[k0 * N + nn],       w01 = W[(k0 + 1) * N + nn];
        float w10 = W[(k0 + 8) * N + nn], w11 = W[(k0 + 9) * N + nn];
        uint4 f;
        SPLIT2(w00, w01, f.x, f.z);
        SPLIT2(w10, w11, f.y, f.w);
        reinterpret_cast<uint4*>(dst)[idx] = f;
    }
}

// GEMM: KT k16-tiles x NT n8-tiles, split-3; k==0 uses zero-source MMA
#define GEMM_LAYER(Dv, Ahv, Alv, KT, NT, OFF) do { \
    _Pragma("unroll") \
    for (int k = 0; k < (KT); k++) { \
        _Pragma("unroll") \
        for (int nt = 0; nt < (NT); nt++) { \
            uint4 _b = lds128(sb + (OFF) + \
                (uint32_t)(((k * (NT) + nt) * 32 + lane) * 16)); \
            if (k == 0) mma_bf16_z(Dv[nt], Ahv[0], _b.x, _b.y, zr); \
            else        mma_bf16(Dv[nt], Ahv[k], _b.x, _b.y); \
            mma_bf16(Dv[nt], Ahv[k], _b.z, _b.w); \
            mma_bf16(Dv[nt], Alv[k], _b.x, _b.y); \
        } \
    } \
} while (0)

// relu + split D[8][4] -> Ah/Al[4][4]
#define EPI_RELU(Dv, Ahv, Alv) do { \
    _Pragma("unroll") \
    for (int j = 0; j < 4; j++) { \
        RELU_SPLIT2(Dv[2*j][0],   Dv[2*j][1],   Ahv[j][0], Alv[j][0]); \
        RELU_SPLIT2(Dv[2*j][2],   Dv[2*j][3],   Ahv[j][1], Alv[j][1]); \
        RELU_SPLIT2(Dv[2*j+1][0], Dv[2*j+1][1], Ahv[j][2], Alv[j][2]); \
        RELU_SPLIT2(Dv[2*j+1][2], Dv[2*j+1][3], Ahv[j][3], Alv[j][3]); \
    } \
} while (0)

__global__ void __launch_bounds__(256, 2)
nerf_hmma12_kernel(const float* __restrict__ x,
                   const float* __restrict__ s0, const float* __restrict__ s1,
                   const float* __restrict__ s2, const float* __restrict__ c0,
                   const float* __restrict__ c1, const float* __restrict__ c2,
                   const float* __restrict__ c3,
                   float* __restrict__ out, int n) {
    extern __shared__ char sm[];
    const uint32_t sb = smem_u32(sm);

    const int tid = threadIdx.x;
    const int wid = tid >> 5;      // 0..7
    const int lane = tid & 31;
    const int q = lane & 3;
    const int nrow = lane >> 2;
    const float zr = 0.0f;

    // ---------- stage split weights in fragment order ----------
    stage_plain(s0, 64, 2, 8, sm + S0F, tid);
    stage_plain(s1, 64, 4, 8, sm + S1F, tid);
    stage_plain(s2, 16, 4, 2, sm + S2F, tid);
    stage_plain(c1, 64, 4, 8, sm + C1F, tid);
    stage_plain(c2, 64, 4, 8, sm + C2F, tid);
    // c0: cat layout [views(16) | zero-row@16 | geo(15)] => K=32
    {
        const int total = 2 * 8 * 32;
        for (int idx = tid; idx < total; idx += 256) {
            int lane2 = idx & 31;
            int grp = idx >> 5;
            int nt = grp % 8, kt = grp / 8;
            int q2 = lane2 & 3, nr = lane2 >> 2;
            int nn = nt * 8 + nr;
            int k0 = kt * 16 + 2 * q2;
            auto w = [&](int k) -> float {
                return (k < 16) ? c0[k * 64 + nn]
                                : ((k == 16) ? 0.0f : c0[(k - 1) * 64 + nn]);
            };
            uint4 f;
            SPLIT2(w(k0),     w(k0 + 1), f.x, f.z);
            SPLIT2(w(k0 + 8), w(k0 + 9), f.y, f.w);
            reinterpret_cast<uint4*>(sm + C0F)[idx] = f;
        }
    }
    // c3 raw fp32, padded [k][4]: {w0, w1, w2, 0} per k row
    for (int k = tid; k < 64; k += 256) {
        float4 w = make_float4(c3[k * 3 + 0], c3[k * 3 + 1], c3[k * 3 + 2], 0.0f);
        reinterpret_cast<float4*>(sm + C3R)[k] = w;
    }
    __syncthreads();

    const int ntiles = (n + 127) >> 7;
    const uint32_t xb = sb + XBUF + (uint32_t)wid * XWARPB;

    // prefetch X for this warp's 16 rows of a tile into its private buffer
    auto prefetch = [&](int tile) {
        int base_r = tile * 128 + wid * 16;
#pragma unroll
        for (int j = 0; j < 6; j++) {
            int c = lane + 32 * j;          // 0..191
            int row = c / 12, col = c % 12; // 12 x 16B chunks per 48-float row
            int r = base_r + row;
            if (r >= n) r = n - 1;
            const char* src = (const char*)(x + (size_t)r * XDIM) + col * 16;
            cp_async16(xb + (uint32_t)(row * XROWB + col * 16), src);
        }
    };

    int tile = blockIdx.x;
    if (tile < ntiles) prefetch(tile);
    CP_COMMIT();

    for (; tile < ntiles; tile += gridDim.x) {
        const int base = tile * 128 + wid * 16;

        uint32_t Ah[4][4], Al[4][4];
        uint32_t Vh[4], Vl[4];
        float D[8][4];
        float sigL, sigH;

        // ---------- consume staged X, build A frags (s0) + view frags ----------
        CP_WAIT0();
        __syncwarp();
        {
            uint32_t a0 = xb + (uint32_t)nrow * XROWB;
            uint32_t a1 = a0 + 8u * XROWB;
#pragma unroll
            for (int t = 0; t < 2; t++) {
                float2 a00 = lds_f2(a0 + 64 * t + 8 * q);
                float2 a10 = lds_f2(a1 + 64 * t + 8 * q);
                float2 a01 = lds_f2(a0 + 64 * t + 8 * q + 32);
                float2 a11 = lds_f2(a1 + 64 * t + 8 * q + 32);
                SPLIT2(a00.x, a00.y, Ah[t][0], Al[t][0]);
                SPLIT2(a10.x, a10.y, Ah[t][1], Al[t][1]);
                SPLIT2(a01.x, a01.y, Ah[t][2], Al[t][2]);
                SPLIT2(a11.x, a11.y, Ah[t][3], Al[t][3]);
            }
            float2 v00 = lds_f2(a0 + 128 + 8 * q);
            float2 v10 = lds_f2(a1 + 128 + 8 * q);
            float2 v01 = lds_f2(a0 + 160 + 8 * q);
            float2 v11 = lds_f2(a1 + 160 + 8 * q);
            SPLIT2(v00.x, v00.y, Vh[0], Vl[0]);
            SPLIT2(v10.x, v10.y, Vh[1], Vl[1]);
            SPLIT2(v01.x, v01.y, Vh[2], Vl[2]);
            SPLIT2(v11.x, v11.y, Vh[3], Vl[3]);
        }
        __syncwarp();

        // kick off next tile's X prefetch; overlaps the whole GEMM chain
        {
            int nxt = tile + gridDim.x;
            if (nxt < ntiles) prefetch(nxt);
            CP_COMMIT();
        }

        // ---------- sigma net ----------
        GEMM_LAYER(D, Ah, Al, 2, 8, S0F);
        EPI_RELU(D, Ah, Al);
        GEMM_LAYER(D, Ah, Al, 4, 8, S1F);
        EPI_RELU(D, Ah, Al);
        GEMM_LAYER(D, Ah, Al, 4, 2, S2F);

        // sigma + cat = [views | s2out raw (col0 hits zero weight row)]
        sigL = D[0][0];
        sigH = D[0][2];
        SPLIT2(D[0][0], D[0][1], Ah[1][0], Al[1][0]);
        SPLIT2(D[0][2], D[0][3], Ah[1][1], Al[1][1]);
        SPLIT2(D[1][0], D[1][1], Ah[1][2], Al[1][2]);
        SPLIT2(D[1][2], D[1][3], Ah[1][3], Al[1][3]);
#pragma unroll
        for (int i = 0; i < 4; i++) { Ah[0][i] = Vh[i]; Al[0][i] = Vl[i]; }

        // ---------- color net ----------
        GEMM_LAYER(D, Ah, Al, 2, 8, C0F);
        EPI_RELU(D, Ah, Al);
        GEMM_LAYER(D, Ah, Al, 4, 8, C1F);
        EPI_RELU(D, Ah, Al);

        // ---------- c2 GEMM nt-major with c3 FMA interleaved per-nt ----------
        // nt-major: each D[nt] receives its 12 MMAs consecutively, then its
        // c3 partial (FMA pipe) issues while later nt tiles' MMAs stream.
        float o0 = 0.f, o1 = 0.f, o2 = 0.f, o3 = 0.f, o4 = 0.f, o5 = 0.f;
#pragma unroll
        for (int nt = 0; nt < 8; nt++) {
#pragma unroll
            for (int k = 0; k < 4; k++) {
                uint4 _b = lds128(sb + C2F +
                    (uint32_t)(((k * 8 + nt) * 32 + lane) * 16));
                if (k == 0) mma_bf16_z(D[nt], Ah[0], _b.x, _b.y, zr);
                else        mma_bf16(D[nt], Ah[k], _b.x, _b.y);
                mma_bf16(D[nt], Ah[k], _b.z, _b.w);
                mma_bf16(D[nt], Al[k], _b.x, _b.y);
            }
            // c3 partial for this nt (exact fp32, FMA pipe)
            uint32_t wa = sb + C3R + (uint32_t)((nt * 8 + 2 * q) * 16);
            float4 w0 = lds_f4v(wa);
            float4 w1 = lds_f4v(wa + 16);
            float h00 = fmaxf(D[nt][0], 0.f), h01 = fmaxf(D[nt][1], 0.f);
            float h10 = fmaxf(D[nt][2], 0.f), h11 = fmaxf(D[nt][3], 0.f);
            o0 = fmaf(h00, w0.x, fmaf(h01, w1.x, o0));
            o1 = fmaf(h00, w0.y, fmaf(h01, w1.y, o1));
            o2 = fmaf(h00, w0.z, fmaf(h01, w1.z, o2));
            o3 = fmaf(h10, w0.x, fmaf(h11, w1.x, o3));
            o4 = fmaf(h10, w0.y, fmaf(h11, w1.y, o4));
            o5 = fmaf(h10, w0.z, fmaf(h11, w1.z, o5));
        }
        // reduce across the 4-lane q-group (lanes q=0..3 hold disjoint cols)
#pragma unroll
        for (int d = 1; d < 4; d <<= 1) {
            o0 += __shfl_xor_sync(0xFFFFFFFFu, o0, d);
            o1 += __shfl_xor_sync(0xFFFFFFFFu, o1, d);
            o2 += __shfl_xor_sync(0xFFFFFFFFu, o2, d);
            o3 += __shfl_xor_sync(0xFFFFFFFFu, o3, d);
            o4 += __shfl_xor_sync(0xFFFFFFFFu, o4, d);
            o5 += __shfl_xor_sync(0xFFFFFFFFu, o5, d);
        }

        // ---------- direct output: q==0 lanes hold complete rows ----------
        if (q == 0) {
            int r0 = base + nrow;
            int r1 = r0 + 8;
            if (r0 < n)
                reinterpret_cast<float4*>(out)[r0] = make_float4(o0, o1, o2, sigL);
            if (r1 < n)
                reinterpret_cast<float4*>(out)[r1] = make_float4(o3, o4, o5, sigH);
        }
    }
}

extern "C" void kernel_launch(void* const* d_in, const int* in_sizes, int n_in,
                              void* d_out, int out_size) {
    const float* x  = (const float*)d_in[0];
    const float* s0 = (const float*)d_in[1];
    const float* s1 = (const float*)d_in[2];
    const float* s2 = (const float*)d_in[3];
    const float* c0 = (const float*)d_in[4];
    const float* c1 = (const float*)d_in[5];
    const float* c2 = (const float*)d_in[6];
    const float* c3 = (const float*)d_in[7];
    float* out = (float*)d_out;

    const int n = in_sizes[0] / XDIM;

    cudaFuncSetAttribute(nerf_hmma12_kernel,
                         cudaFuncAttributeMaxDynamicSharedMemorySize, SMEM_TOTAL);

    int occ = 0;
    cudaOccupancyMaxActiveBlocksPerMultiprocessor(&occ, nerf_hmma12_kernel, 256,
                                                  SMEM_TOTAL);
    if (occ < 1) occ = 1;
    int blocks = 152 * occ;

    nerf_hmma12_kernel<<<blocks, 256, SMEM_TOTAL>>>(x, s0, s1, s2, c0, c1, c2,
                                                    c3, out, n);
}